// round 7
// baseline (speedup 1.0000x reference)
#include <cuda_runtime.h>
#include <cuda_fp16.h>
#include <cstdint>

// Fourier-KAN: out[b,o] = bias[o] + sum_{i,k} cos(k x[b,i]) c0[i,o,k-1] + sin(k x) c1[i,o,k-1]
// B=32768, I=512, O=64, G=8  ->  GEMM M=32768, N=64, K=8192, fp16 features on the fly.
// R7: 768 threads. 16 MMA consumer warps (32 rows x 32 cols, full K, acc=32 regs)
// + 8 producer warps (sincos features + B cp.async). KC=128 (half the barrier
// round-trips), 2-stage mbarrier ring. Interleaved (cos,sin) K layout.

#define NB 32768
#define NI 512
#define NO 64
#define NG 8
#define KTOT 8192
#define MCTA 256
#define KC 128             // K per chunk = 8 i-values * 16 features
#define NCHUNK 64
#define NTHREADS 768
#define STAGES 2

#define ASUB 32768                 // one A k-subtile: 256 rows x 128B
#define BSUB 8192                  // one B k-subtile: 64 rows x 128B
#define ABYTES (2 * ASUB)          // 64 KB
#define BUFSZ (ABYTES + 2 * BSUB)  // 80 KB
#define SMEM_BUF0 1024
#define SMEM_TOTAL (SMEM_BUF0 + STAGES * BUFSZ)   // 164864 B

// repacked coeffs: Wt[o][k], k = i*16 + 2g + t; t=0: cos freq g+1, t=1: sin freq g+1
__device__ __half g_Wt[NO * KTOT];

// ---------------- helpers ----------------
__device__ __forceinline__ uint32_t smem_u32(const void* p) {
    uint32_t a;
    asm("{ .reg .u64 t; cvta.to.shared.u64 t, %1; cvt.u32.u64 %0, t; }" : "=r"(a) : "l"(p));
    return a;
}

#define SW128(o) ((o) ^ (((o) >> 3) & 0x70))

#define LDSM_X4(r0, r1, r2, r3, addr) \
    asm volatile("ldmatrix.sync.aligned.m8n8.x4.shared.b16 {%0,%1,%2,%3}, [%4];" \
                 : "=r"(r0), "=r"(r1), "=r"(r2), "=r"(r3) : "r"(addr))

#define CP_ASYNC16(dst, src) \
    asm volatile("cp.async.ca.shared.global [%0], [%1], 16;" \
                 :: "r"(dst), "l"(src) : "memory")
#define CP_COMMIT() asm volatile("cp.async.commit_group;" ::: "memory")
#define CP_WAIT0()  asm volatile("cp.async.wait_group 0;" ::: "memory")

#define MBAR_INIT(a, c) \
    asm volatile("mbarrier.init.shared.b64 [%0], %1;" :: "r"((uint32_t)(a)), "r"((uint32_t)(c)) : "memory")
#define MBAR_ARRIVE(a) \
    asm volatile("mbarrier.arrive.shared.b64 _, [%0];" :: "r"((uint32_t)(a)) : "memory")

#define MBAR_WAIT_PARITY(addr, parity) do {                                        \
    uint32_t _mbar = (uint32_t)(addr);                                             \
    uint32_t _par = (uint32_t)(parity);                                            \
    uint32_t _done;                                                                \
    asm volatile("{\n\t.reg .pred p;\n\t"                                          \
        "mbarrier.try_wait.parity.acquire.cta.shared::cta.b64 p, [%1], %2;\n\t"    \
        "selp.b32 %0, 1, 0, p;\n\t}"                                               \
        : "=r"(_done) : "r"(_mbar), "r"(_par) : "memory");                         \
    if (!_done) {                                                                  \
        asm volatile("{\n\t.reg .pred P1;\n\t"                                     \
            "WAIT_LOOP_%=:\n\t"                                                    \
            "mbarrier.try_wait.parity.acquire.cta.shared::cta.b64 P1, [%0], %1, 0x989680;\n\t" \
            "@P1 bra.uni WAIT_DONE_%=;\n\t"                                        \
            "bra.uni WAIT_LOOP_%=;\n\t"                                            \
            "WAIT_DONE_%=:\n\t}"                                                   \
            :: "r"(_mbar), "r"(_par) : "memory");                                  \
    }                                                                              \
} while (0)

__device__ __forceinline__ void mma16816(float* d, const uint32_t* a,
                                         uint32_t b0, uint32_t b1) {
    asm volatile(
        "mma.sync.aligned.m16n8k16.row.col.f32.f16.f16.f32 "
        "{%0,%1,%2,%3}, {%4,%5,%6,%7}, {%8,%9}, {%0,%1,%2,%3};"
        : "+f"(d[0]), "+f"(d[1]), "+f"(d[2]), "+f"(d[3])
        : "r"(a[0]), "r"(a[1]), "r"(a[2]), "r"(a[3]), "r"(b0), "r"(b1));
}

// ---------------- prep: repack coeffs (2,I,O,G) f32 -> Wt[o][k] fp16 ----------------
// k = i*16 + 2g + t (interleaved cos/sin)
__global__ void fkan_prep(const float* __restrict__ cf) {
    int idx = blockIdx.x * blockDim.x + threadIdx.x;
    if (idx >= NO * KTOT) return;
    int o = idx >> 13;
    int k = idx & (KTOT - 1);
    int i = k >> 4;
    int f = k & 15;
    int g = f >> 1;               // freq-1
    int t = f & 1;                // 0 = cos, 1 = sin
    float v = cf[(((t * NI) + i) * NO + o) * NG + g];
    g_Wt[o * KTOT + k] = __float2half(v);
}

// ---------------- main fused kernel ----------------
__global__ void __launch_bounds__(NTHREADS, 1)
fkan_main(const float* __restrict__ x, const float* __restrict__ bias,
          float* __restrict__ out) {
    extern __shared__ __align__(1024) char smem[];
    const uint32_t sbase = smem_u32(smem);

    const int tid = threadIdx.x;
    const int w = tid >> 5;
    const int lane = tid & 31;

    // barriers: full[s] at s*16, empty[s] at s*16+8
    if (tid == 0) {
        #pragma unroll
        for (int s = 0; s < STAGES; ++s) {
            MBAR_INIT(sbase + s * 16, 256);       // full: 256 producer threads
            MBAR_INIT(sbase + s * 16 + 8, 512);   // empty: 512 consumer threads
        }
    }
    __syncthreads();

    if (w < 16) {
        // ================= CONSUMER: MMA warps =================
        const int mw = w & 7;               // rows mw*32 .. +31
        const int nh = w >> 3;              // cols nh*32 .. +31
        const uint32_t a_ls0 = SW128((uint32_t)((mw * 32 + (lane & 15)) * 128 +
                                                ((lane >> 4) << 4)));
        const uint32_t a_ls1 = SW128((uint32_t)((mw * 32 + 16 + (lane & 15)) * 128 +
                                                ((lane >> 4) << 4)));
        const uint32_t bl = (uint32_t)((lane & 7) + ((lane >> 4) << 3));
        const uint32_t bbo = (uint32_t)(((lane >> 3) & 1) << 4);
        const uint32_t b_ls0 = SW128((uint32_t)((nh * 32 + bl) * 128) + bbo);
        const uint32_t b_ls1 = SW128((uint32_t)((nh * 32 + 16 + bl) * 128) + bbo);

        float acc[2][4][4];
        #pragma unroll
        for (int mi = 0; mi < 2; ++mi)
            #pragma unroll
            for (int j = 0; j < 4; ++j)
                #pragma unroll
                for (int q = 0; q < 4; ++q) acc[mi][j][q] = 0.0f;

        int s = 0, mpar = 0;
        #pragma unroll 1
        for (int c = 0; c < NCHUNK; ++c) {
            MBAR_WAIT_PARITY(sbase + s * 16, mpar);            // wait full[s]
            const uint32_t buf = sbase + SMEM_BUF0 + (uint32_t)s * BUFSZ;

            #pragma unroll
            for (int kb = 0; kb < 2; ++kb) {
                const uint32_t aB = buf + (uint32_t)kb * ASUB;
                const uint32_t bB = buf + ABYTES + (uint32_t)kb * BSUB;
                #pragma unroll
                for (int ks = 0; ks < 4; ++ks) {
                    const uint32_t kx = (uint32_t)(ks << 5);
                    uint32_t a0[4], a1[4], b0[4], b1[4];
                    LDSM_X4(a0[0], a0[1], a0[2], a0[3], aB + (a_ls0 ^ kx));
                    LDSM_X4(a1[0], a1[1], a1[2], a1[3], aB + (a_ls1 ^ kx));
                    LDSM_X4(b0[0], b0[1], b0[2], b0[3], bB + (b_ls0 ^ kx));
                    LDSM_X4(b1[0], b1[1], b1[2], b1[3], bB + (b_ls1 ^ kx));
                    #pragma unroll
                    for (int j = 0; j < 4; ++j) {
                        const uint32_t* bp = (j < 2) ? b0 : b1;
                        const int hi = (j & 1) << 1;
                        mma16816(acc[0][j], a0, bp[hi], bp[hi + 1]);
                        mma16816(acc[1][j], a1, bp[hi], bp[hi + 1]);
                    }
                }
            }

            MBAR_ARRIVE(sbase + s * 16 + 8);                   // arrive empty[s]
            if (++s == STAGES) { s = 0; mpar ^= 1; }
        }

        // ---- epilogue: acc (+bias) -> out ----
        const int gr = lane >> 2;
        const int gc = (lane & 3) << 1;
        #pragma unroll
        for (int mi = 0; mi < 2; ++mi) {
            const int row0 = blockIdx.x * MCTA + mw * 32 + mi * 16 + gr;
            #pragma unroll
            for (int j = 0; j < 4; ++j) {
                const int col = nh * 32 + j * 8 + gc;
                float2 bb2 = *(const float2*)(bias + col);
                float2 v0, v1;
                v0.x = acc[mi][j][0] + bb2.x; v0.y = acc[mi][j][1] + bb2.y;
                v1.x = acc[mi][j][2] + bb2.x; v1.y = acc[mi][j][3] + bb2.y;
                *(float2*)(out + (size_t)row0 * NO + col) = v0;
                *(float2*)(out + (size_t)(row0 + 8) * NO + col) = v1;
            }
        }
    } else {
        // ================= PRODUCER: feature warps =================
        const int p = tid - 512;            // 0..255
        const int row = p;
        const float* xrow = x + ((size_t)(blockIdx.x * MCTA + row)) * NI;
        uint32_t fst[8];                    // STS addrs for iloc&3 = 0..3, two 16B halves
        #pragma unroll
        for (int j = 0; j < 4; ++j) {
            fst[2 * j]     = SW128((uint32_t)(row * 128 + j * 32));
            fst[2 * j + 1] = SW128((uint32_t)(row * 128 + j * 32 + 16));
        }
        // B loader: row bo, 4 consecutive 16B units starting at bu*4
        const int bo = p >> 2;
        const int bu = p & 3;
        const __half* wsrc = g_Wt + bo * KTOT + bu * 4 * 8;
        uint32_t b_st[4];
        #pragma unroll
        for (int q = 0; q < 4; ++q) {
            const int unit = bu * 4 + q;            // 0..15
            const int sub = unit >> 3;              // k-subtile
            const int ul = unit & 7;
            b_st[q] = (uint32_t)(ABYTES + sub * BSUB) +
                      SW128((uint32_t)(bo * 128 + ul * 16));
        }

        float4 xa = *(const float4*)(xrow);
        float4 xb = *(const float4*)(xrow + 4);

        int s = 0, mpar = 0;
        #pragma unroll 1
        for (int c = 0; c < NCHUNK; ++c) {
            // prefetch next chunk's x (clamped)
            const int cp = (c + 1 < NCHUNK) ? c + 1 : NCHUNK - 1;
            float4 xan = *(const float4*)(xrow + cp * 8);
            float4 xbn = *(const float4*)(xrow + cp * 8 + 4);

            MBAR_WAIT_PARITY(sbase + s * 16 + 8, mpar ^ 1);    // wait empty[s]
            const uint32_t bufb = (uint32_t)(SMEM_BUF0) + (uint32_t)s * BUFSZ;
            const uint32_t bufa = sbase + bufb;

            // B via cp.async: 4 x 16B
            #pragma unroll
            for (int q = 0; q < 4; ++q)
                CP_ASYNC16(bufa + b_st[q], wsrc + (size_t)c * KC + q * 8);
            CP_COMMIT();

            // A features: 8 i-units for this row
            const float xs[8] = {xa.x, xa.y, xa.z, xa.w, xb.x, xb.y, xb.z, xb.w};
            #pragma unroll
            for (int il = 0; il < 8; ++il) {
                float s1, c1;
                __sincosf(xs[il], &s1, &c1);
                float t2 = c1 + c1;
                float ck[8], sk[8];
                ck[0] = c1; sk[0] = s1;
                float cm2 = 1.0f, sm2 = 0.0f;
                #pragma unroll
                for (int k = 1; k < 8; ++k) {
                    float cn = fmaf(t2, ck[k - 1], -cm2);
                    float sn = fmaf(t2, sk[k - 1], -sm2);
                    cm2 = ck[k - 1]; sm2 = sk[k - 1];
                    ck[k] = cn; sk[k] = sn;
                }
                // interleaved (cos_k, sin_k) half2 per harmonic
                __half2 h[8];
                #pragma unroll
                for (int k = 0; k < 8; ++k)
                    h[k] = __floats2half2_rn(ck[k], sk[k]);
                uint4 v0, v1;
                v0.x = *(uint32_t*)&h[0]; v0.y = *(uint32_t*)&h[1];
                v0.z = *(uint32_t*)&h[2]; v0.w = *(uint32_t*)&h[3];
                v1.x = *(uint32_t*)&h[4]; v1.y = *(uint32_t*)&h[5];
                v1.z = *(uint32_t*)&h[6]; v1.w = *(uint32_t*)&h[7];
                const uint32_t so = bufb + (uint32_t)((il >> 2) * ASUB);
                *(uint4*)(smem + so + fst[2 * (il & 3)]) = v0;
                *(uint4*)(smem + so + fst[2 * (il & 3) + 1]) = v1;
            }

            CP_WAIT0();
            MBAR_ARRIVE(sbase + s * 16);       // arrive full[s]

            xa = xan; xb = xbn;
            if (++s == STAGES) { s = 0; mpar ^= 1; }
        }
    }
}

// ---------------- launch ----------------
extern "C" void kernel_launch(void* const* d_in, const int* in_sizes, int n_in,
                              void* d_out, int out_size) {
    const float* x    = (const float*)d_in[0];
    const float* cf   = (const float*)d_in[1];
    const float* bias = (const float*)d_in[2];
    float* out        = (float*)d_out;

    static bool attr_set = false;
    if (!attr_set) {
        cudaFuncSetAttribute(fkan_main, cudaFuncAttributeMaxDynamicSharedMemorySize,
                             SMEM_TOTAL);
        attr_set = true;
    }

    fkan_prep<<<(NO * KTOT + 255) / 256, 256>>>(cf);
    fkan_main<<<NB / MCTA, NTHREADS, SMEM_TOTAL>>>(x, bias, out);
}